// round 1
// baseline (speedup 1.0000x reference)
#include <cuda_runtime.h>

#define BB 8
#define HH 256
#define KK 256
#define EE 128

// scratch for per-(b,h) attention outputs: 8*256*128 floats = 1 MB
__device__ float g_o[BB * HH * EE];

__global__ __launch_bounds__(128)
void kvmem_phase1(const float* __restrict__ hidden,
                  const float* __restrict__ key_emb,
                  const float* __restrict__ value_emb,
                  const int*   __restrict__ key_seq,
                  const int*   __restrict__ value_seq,
                  const int*   __restrict__ mask)
{
    const int h   = blockIdx.x;
    const int b   = blockIdx.y;
    const int t   = threadIdx.x;      // 0..127
    const int wid = t >> 5;
    const int lid = t & 31;

    __shared__ float s_hidden[EE];
    __shared__ float s_p[KK];      // holds u, then p
    __shared__ int   s_kidx[KK];
    __shared__ int   s_vidx[KK];
    __shared__ float s_red[4];
    __shared__ float s_sum;

    // stage hidden row + gather indices
    s_hidden[t] = hidden[(b * HH + h) * EE + t];
    #pragma unroll
    for (int k = t; k < KK; k += 128) {
        s_kidx[k] = key_seq[b * KK + k];
        s_vidx[k] = value_seq[(b * HH + h) * KK + k];
    }
    __syncthreads();

    const float inv_scale = 0.08838834764831845f;  // 1/sqrt(128)

    // Phase A: u[k] = <hidden, key_emb[kidx]> / sqrt(E); warp per k, 4 warps round-robin
    for (int k = wid; k < KK; k += 4) {
        const float* krow = key_emb + (long)s_kidx[k] * EE;
        float acc = 0.f;
        #pragma unroll
        for (int j = 0; j < 4; j++)
            acc = fmaf(s_hidden[lid + 32 * j], krow[lid + 32 * j], acc);
        #pragma unroll
        for (int m = 16; m > 0; m >>= 1)
            acc += __shfl_xor_sync(0xffffffffu, acc, m);
        if (lid == 0) s_p[k] = acc * inv_scale;
    }
    __syncthreads();

    // delta = exp(u) * mask ; block-sum ; p = delta / (sum + 1e-10)
    const int mbase = (b * HH + h) * KK;
    float d0 = expf(s_p[t])       * (float)mask[mbase + t];
    float d1 = expf(s_p[t + 128]) * (float)mask[mbase + t + 128];
    float d  = d0 + d1;
    #pragma unroll
    for (int m = 16; m > 0; m >>= 1)
        d += __shfl_xor_sync(0xffffffffu, d, m);
    if (lid == 0) s_red[wid] = d;
    __syncthreads();
    if (t == 0) s_sum = s_red[0] + s_red[1] + s_red[2] + s_red[3] + 1e-10f;
    __syncthreads();
    const float inv = 1.0f / s_sum;
    s_p[t]       = d0 * inv;
    s_p[t + 128] = d1 * inv;
    __syncthreads();

    // Phase B: o[e] = sum_k p[k] * value_emb[vidx[k]][e]; thread t owns e=t.
    // Unrolled for MLP — value_emb (512 KB) lives in L2.
    float acc = 0.f;
    #pragma unroll 8
    for (int k = 0; k < KK; k++) {
        acc = fmaf(s_p[k], value_emb[(long)s_vidx[k] * EE + t], acc);
    }
    g_o[(b * HH + h) * EE + t] = acc;
}

__global__ __launch_bounds__(128)
void kvmem_phase2(float* __restrict__ out)
{
    const int b = blockIdx.x;
    const int t = threadIdx.x;  // e
    float sum = 0.f;
    float cnt = 0.f;
    #pragma unroll 8
    for (int h = 0; h < HH; h++) {
        float v = g_o[(b * HH + h) * EE + t];
        sum += v;
        cnt += (v != 0.0f) ? 1.0f : 0.0f;
    }
    out[b * EE + t] = sum / cnt;   // reference has no epsilon here
}

extern "C" void kernel_launch(void* const* d_in, const int* in_sizes, int n_in,
                              void* d_out, int out_size)
{
    const float* hidden    = (const float*)d_in[0];
    const float* key_emb   = (const float*)d_in[1];
    const float* value_emb = (const float*)d_in[2];
    const int*   key_seq   = (const int*)d_in[3];
    const int*   value_seq = (const int*)d_in[4];
    const int*   mask      = (const int*)d_in[5];
    float* out = (float*)d_out;

    dim3 g1(HH, BB);
    kvmem_phase1<<<g1, 128>>>(hidden, key_emb, value_emb, key_seq, value_seq, mask);
    kvmem_phase2<<<BB, EE>>>(out);
}

// round 2
// speedup vs baseline: 1.0028x; 1.0028x over previous
#include <cuda_runtime.h>

#define BB 8
#define HH 256
#define KK 256
#define EE 128
#define TH 8                 // heads per CTA
#define NT (HH / TH)         // 32 head-tiles

// per-tile partial sums and nonzero counts: [B][NT][E]
__device__ float g_psum[BB * NT * EE];
__device__ float g_pcnt[BB * NT * EE];

__global__ __launch_bounds__(256)
void kvmem_phase1(const float* __restrict__ hidden,
                  const float* __restrict__ key_emb,
                  const float* __restrict__ value_emb,
                  const int*   __restrict__ key_seq,
                  const int*   __restrict__ value_seq,
                  const int*   __restrict__ mask)
{
    const int htile = blockIdx.x;          // 0..31
    const int b     = blockIdx.y;          // 0..7
    const int h0    = htile * TH;
    const int t     = threadIdx.x;         // 0..255
    const int w     = t >> 5;              // 0..7
    const int lid   = t & 31;

    __shared__ float         s_hid[TH][EE];     // 4 KB
    __shared__ float         s_p[TH][KK];       // 8 KB: u -> delta -> (delta used with s_inv)
    __shared__ int           s_vidx[TH][KK];    // 8 KB
    __shared__ int           s_kidx[KK];        // 1 KB
    __shared__ unsigned char s_msk[TH][KK];     // 2 KB
    __shared__ float         s_inv[TH];
    __shared__ float         s_o[TH][EE];       // 4 KB

    // ---- stage inputs ----
    #pragma unroll
    for (int i = t; i < TH * EE; i += 256)
        s_hid[i >> 7][i & 127] = hidden[(b * HH + h0 + (i >> 7)) * EE + (i & 127)];
    #pragma unroll
    for (int i = t; i < TH * KK; i += 256)
        s_vidx[i >> 8][i & 255] = value_seq[(b * HH + h0 + (i >> 8)) * KK + (i & 255)];
    s_kidx[t] = key_seq[b * KK + t];            // t spans 0..255 == KK
    #pragma unroll
    for (int hh = 0; hh < TH; hh++) {
        int m = mask[(b * HH + h0 + hh) * KK + t];
        s_msk[hh][t] = (unsigned char)m;
        s_p[hh][t]   = 0.0f;                    // default for masked entries
    }
    __syncthreads();

    const float inv_scale = 0.08838834764831845f;   // 1/sqrt(128)

    // ---- Phase A: u[hh][k] = <hidden[hh], key_emb[kidx[k]]>/sqrt(E)
    // warp w handles k = w, w+8, ...; row loaded coalesced (float4/lane)
    for (int k = w; k < KK; k += 8) {
        const float4* krow = (const float4*)(key_emb + (size_t)s_kidx[k] * EE);
        float4 kv = krow[lid];
        #pragma unroll
        for (int hh = 0; hh < TH; hh++) {
            if (s_msk[hh][k]) {                 // warp-uniform: skip masked dots
                float4 hv = ((const float4*)s_hid[hh])[lid];
                float d = kv.x * hv.x + kv.y * hv.y + kv.z * hv.z + kv.w * hv.w;
                #pragma unroll
                for (int m = 16; m > 0; m >>= 1)
                    d += __shfl_xor_sync(0xffffffffu, d, m);
                if (lid == 0) s_p[hh][k] = d * inv_scale;
            }
        }
    }
    __syncthreads();

    // ---- delta = exp(u)*mask (in place); thread t owns k = t
    #pragma unroll
    for (int hh = 0; hh < TH; hh++) {
        float d = s_msk[hh][t] ? expf(s_p[hh][t]) : 0.0f;
        s_p[hh][t] = d;
    }
    __syncthreads();

    // ---- row sums: warp w reduces head w
    {
        float sacc = 0.0f;
        #pragma unroll
        for (int j = 0; j < KK / 32; j++)
            sacc += s_p[w][lid + 32 * j];
        #pragma unroll
        for (int m = 16; m > 0; m >>= 1)
            sacc += __shfl_xor_sync(0xffffffffu, sacc, m);
        if (lid == 0) s_inv[w] = 1.0f / (sacc + 1e-10f);
    }
    __syncthreads();

    // ---- Phase B: warp w owns head hh = w; per-lane float4 accumulator (e = 4*lid..)
    {
        const int hh = w;
        float4 acc = make_float4(0.f, 0.f, 0.f, 0.f);
        #pragma unroll 4
        for (int k = 0; k < KK; k++) {
            float pk = s_p[hh][k];              // warp-uniform broadcast
            if (pk != 0.0f) {                   // skip masked/zero weights (~50%)
                const float4* vrow = (const float4*)(value_emb + (size_t)s_vidx[hh][k] * EE);
                float4 v = vrow[lid];
                acc.x += pk * v.x;
                acc.y += pk * v.y;
                acc.z += pk * v.z;
                acc.w += pk * v.w;
            }
        }
        float iv = s_inv[hh];
        acc.x *= iv; acc.y *= iv; acc.z *= iv; acc.w *= iv;
        ((float4*)s_o[hh])[lid] = acc;
    }
    __syncthreads();

    // ---- per-tile partial H-reduction: sum + nonzero count over 8 heads
    if (t < EE) {
        float sum = 0.0f, cnt = 0.0f;
        #pragma unroll
        for (int hh = 0; hh < TH; hh++) {
            float v = s_o[hh][t];
            sum += v;
            cnt += (v != 0.0f) ? 1.0f : 0.0f;
        }
        int o = (b * NT + htile) * EE + t;
        g_psum[o] = sum;
        g_pcnt[o] = cnt;
    }
}

__global__ __launch_bounds__(128)
void kvmem_phase2(float* __restrict__ out)
{
    const int b = blockIdx.x;
    const int t = threadIdx.x;      // e
    float sum = 0.0f, cnt = 0.0f;
    #pragma unroll
    for (int nt = 0; nt < NT; nt++) {
        sum += g_psum[(b * NT + nt) * EE + t];
        cnt += g_pcnt[(b * NT + nt) * EE + t];
    }
    out[b * EE + t] = sum / cnt;    // reference adds no epsilon here
}

extern "C" void kernel_launch(void* const* d_in, const int* in_sizes, int n_in,
                              void* d_out, int out_size)
{
    const float* hidden    = (const float*)d_in[0];
    const float* key_emb   = (const float*)d_in[1];
    const float* value_emb = (const float*)d_in[2];
    const int*   key_seq   = (const int*)d_in[3];
    const int*   value_seq = (const int*)d_in[4];
    const int*   mask      = (const int*)d_in[5];
    float* out = (float*)d_out;

    dim3 g1(NT, BB);    // 32 x 8 = 256 CTAs
    kvmem_phase1<<<g1, 256>>>(hidden, key_emb, value_emb, key_seq, value_seq, mask);
    kvmem_phase2<<<BB, EE>>>(out);
}

// round 3
// speedup vs baseline: 1.7517x; 1.7469x over previous
#include <cuda_runtime.h>

#define BB 8
#define HH 256
#define KK 256
#define EE 128
#define KT 16                 // keys per scores-tile
#define NKT (KK / KT)         // 16 tiles

__device__ float g_delta[BB * HH * KK];   // exp(u)  [b][h][k]  (2 MB)
__device__ float g_o[BB * HH * EE];       // per-head outputs   (1 MB)

// ---------------- Kernel A: scores ----------------
// u[b,h,k] = <hidden[b,h], key_emb[key_seq[b,k]]> / sqrt(E);  g_delta = exp(u)
// grid (NKT, BB), 256 threads; thread t == head h; 16 key rows staged in smem.
__global__ __launch_bounds__(256)
void kvmem_scores(const float* __restrict__ hidden,
                  const float* __restrict__ key_emb,
                  const int*   __restrict__ key_seq)
{
    const int kt = blockIdx.x;
    const int b  = blockIdx.y;
    const int t  = threadIdx.x;            // h

    __shared__ float4 s_key[KT][32];       // 8 KB, read broadcast (conflict-free)

    for (int i = t; i < KT * 32; i += 256) {
        int k  = i >> 5;
        int e4 = i & 31;
        int row = key_seq[b * KK + kt * KT + k];
        s_key[k][e4] = ((const float4*)(key_emb + (size_t)row * EE))[e4];
    }
    __syncthreads();

    float acc[KT];
    #pragma unroll
    for (int k = 0; k < KT; k++) acc[k] = 0.f;

    const float4* hrow = (const float4*)(hidden + ((size_t)b * HH + t) * EE);
    #pragma unroll 4
    for (int e4 = 0; e4 < 32; e4++) {
        float4 hv = hrow[e4];
        #pragma unroll
        for (int k = 0; k < KT; k++) {
            float4 kv = s_key[k][e4];
            acc[k] = fmaf(hv.x, kv.x, acc[k]);
            acc[k] = fmaf(hv.y, kv.y, acc[k]);
            acc[k] = fmaf(hv.z, kv.z, acc[k]);
            acc[k] = fmaf(hv.w, kv.w, acc[k]);
        }
    }

    const float inv_scale = 0.08838834764831845f;   // 1/sqrt(128)
    float* drow = g_delta + ((size_t)b * HH + t) * KK + kt * KT;
    #pragma unroll
    for (int k = 0; k < KT; k++)
        drow[k] = expf(acc[k] * inv_scale);
}

// ---------------- Kernel B: normalize + value aggregation ----------------
// grid (HH, BB) = 2048 CTAs, 128 threads; thread t owns output column e=t.
// Nonzero-k list built with deterministic ballot compaction -> branch-free gather.
__global__ __launch_bounds__(128)
void kvmem_agg(const float* __restrict__ value_emb,
               const int*   __restrict__ value_seq,
               const int*   __restrict__ mask)
{
    const int h   = blockIdx.x;
    const int b   = blockIdx.y;
    const int t   = threadIdx.x;
    const int w   = t >> 5;
    const int lid = t & 31;
    const int base = (b * HH + h) * KK;

    __shared__ float s_d[KK];        // masked delta
    __shared__ int   s_vidx[KK];
    __shared__ float s_pc[KK];       // compacted p
    __shared__ int   s_vl[KK];       // compacted vidx
    __shared__ float s_red[4];
    __shared__ int   s_cnt[8];
    __shared__ int   s_basec[8];
    __shared__ float s_invv;
    __shared__ int   s_n;

    // stage masked delta + vidx; partial sum
    float part = 0.f;
    #pragma unroll
    for (int k = t; k < KK; k += 128) {
        float d = g_delta[base + k] * (float)mask[base + k];
        s_d[k] = d;
        s_vidx[k] = value_seq[base + k];
        part += d;
    }
    #pragma unroll
    for (int m = 16; m > 0; m >>= 1)
        part += __shfl_xor_sync(0xffffffffu, part, m);
    if (lid == 0) s_red[w] = part;
    __syncthreads();
    if (t == 0)
        s_invv = 1.0f / (s_red[0] + s_red[1] + s_red[2] + s_red[3] + 1e-10f);
    __syncthreads();
    const float inv = s_invv;

    // ballot compaction: 8 chunks of 32 k; warp w handles chunks 2w, 2w+1
    unsigned bal[2];
    #pragma unroll
    for (int c2 = 0; c2 < 2; c2++) {
        int c = 2 * w + c2;
        float d = s_d[c * 32 + lid];
        bal[c2] = __ballot_sync(0xffffffffu, d > 0.f);
        if (lid == 0) s_cnt[c] = __popc(bal[c2]);
    }
    __syncthreads();
    if (t == 0) {
        int run = 0;
        #pragma unroll
        for (int c = 0; c < 8; c++) { s_basec[c] = run; run += s_cnt[c]; }
        s_n = run;
    }
    __syncthreads();
    #pragma unroll
    for (int c2 = 0; c2 < 2; c2++) {
        int c = 2 * w + c2;
        int k = c * 32 + lid;
        float d = s_d[k];
        if (d > 0.f) {
            int pos = s_basec[c] + __popc(bal[c2] & ((1u << lid) - 1u));
            s_pc[pos] = d * inv;     // pre-normalized weight
            s_vl[pos] = s_vidx[k];
        }
    }
    __syncthreads();

    // branch-free gather over compacted list, unroll 8 for MLP
    const int n = s_n;
    float acc = 0.f;
    int i = 0;
    for (; i + 8 <= n; i += 8) {
        #pragma unroll
        for (int j = 0; j < 8; j++)
            acc = fmaf(s_pc[i + j],
                       __ldg(value_emb + (size_t)s_vl[i + j] * EE + t), acc);
    }
    for (; i < n; i++)
        acc = fmaf(s_pc[i], __ldg(value_emb + (size_t)s_vl[i] * EE + t), acc);

    g_o[((size_t)b * HH + h) * EE + t] = acc;
}

// ---------------- Kernel C: H-reduction with nonzero count ----------------
// grid (4, BB) = 32 CTAs, 256 threads; CTA (eq,b) covers e in [32eq, 32eq+32).
__global__ __launch_bounds__(256)
void kvmem_reduce(float* __restrict__ out)
{
    const int eq  = blockIdx.x;           // 0..3
    const int b   = blockIdx.y;
    const int t   = threadIdx.x;
    const int w   = t >> 5;               // 0..7
    const int lid = t & 31;

    float sum = 0.f, cnt = 0.f;
    for (int hh = w; hh < HH; hh += 8) {
        float v = g_o[((size_t)b * HH + hh) * EE + eq * 32 + lid];
        sum += v;
        cnt += (v != 0.f) ? 1.f : 0.f;
    }

    __shared__ float s_s[8][32];
    __shared__ float s_c[8][32];
    s_s[w][lid] = sum;
    s_c[w][lid] = cnt;
    __syncthreads();
    if (w == 0) {
        float S = 0.f, C = 0.f;
        #pragma unroll
        for (int j = 0; j < 8; j++) { S += s_s[j][lid]; C += s_c[j][lid]; }
        out[b * EE + eq * 32 + lid] = S / C;   // reference adds no epsilon here
    }
}

extern "C" void kernel_launch(void* const* d_in, const int* in_sizes, int n_in,
                              void* d_out, int out_size)
{
    const float* hidden    = (const float*)d_in[0];
    const float* key_emb   = (const float*)d_in[1];
    const float* value_emb = (const float*)d_in[2];
    const int*   key_seq   = (const int*)d_in[3];
    const int*   value_seq = (const int*)d_in[4];
    const int*   mask      = (const int*)d_in[5];
    float* out = (float*)d_out;

    kvmem_scores<<<dim3(NKT, BB), 256>>>(hidden, key_emb, key_seq);
    kvmem_agg<<<dim3(HH, BB), 128>>>(value_emb, value_seq, mask);
    kvmem_reduce<<<dim3(4, BB), 256>>>(out);
}